// round 13
// baseline (speedup 1.0000x reference)
#include <cuda_runtime.h>
#include <cuda_fp16.h>
#include <cstdint>
#include <math.h>

#define BB 2
#define SS 2048
#define HIDN 1280
#define NH 20
#define HD 64

// Scratch (alloc-free rule: __device__ globals)
__device__ float g_Q[BB*NH*SS*HD];
__device__ float g_K[BB*NH*SS*HD];
__device__ float g_V[BB*NH*SS*HD];
__device__ unsigned g_Qh[BB*NH*SS*HD/2];     // Q fp16 (half2-packed along d)
__device__ unsigned g_Kf[BB*NH*SS*HD/2];     // K fp16, per-lane mma B-frag order
__device__ unsigned g_Vf[BB*NH*SS*HD/2];     // V fp16, per-lane mma B-frag order
__device__ unsigned g_Xh[BB*SS*HIDN/2];      // hidden states fp16
__device__ unsigned g_Wth[3*HIDN*HIDN/2];    // transposed weights fp16 ([n][k])
__device__ float g_cos[SS*32];
__device__ float g_sin[SS*32];

// ---------------------------------------------------------------------------
// helpers
// ---------------------------------------------------------------------------
__device__ __forceinline__ unsigned packh2(float x, float y) {
    __half2 h = __floats2half2_rn(x, y);
    return *reinterpret_cast<unsigned*>(&h);
}

__device__ __forceinline__ void mma_f16(float c[4], const unsigned a[4],
                                        unsigned b0, unsigned b1) {
    asm volatile(
        "mma.sync.aligned.m16n8k16.row.col.f32.f16.f16.f32 "
        "{%0,%1,%2,%3}, {%4,%5,%6,%7}, {%8,%9}, {%0,%1,%2,%3};"
        : "+f"(c[0]), "+f"(c[1]), "+f"(c[2]), "+f"(c[3])
        : "r"(a[0]), "r"(a[1]), "r"(a[2]), "r"(a[3]),
          "r"(b0), "r"(b1));
}

__device__ __forceinline__ void ldm_x4(unsigned r[4], unsigned addr) {
    asm volatile(
        "ldmatrix.sync.aligned.m8n8.x4.shared.b16 {%0,%1,%2,%3}, [%4];"
        : "=r"(r[0]), "=r"(r[1]), "=r"(r[2]), "=r"(r[3])
        : "r"(addr));
}

__device__ __forceinline__ void cp16(unsigned int dst, const void* src) {
    asm volatile("cp.async.cg.shared.global [%0], [%1], 16;\n"
                 :: "r"(dst), "l"(src));
}
__device__ __forceinline__ void cp_commit() {
    asm volatile("cp.async.commit_group;\n" ::: "memory");
}
template <int N>
__device__ __forceinline__ void cp_wait() {
    asm volatile("cp.async.wait_group %0;\n" :: "n"(N) : "memory");
}

// ---------------------------------------------------------------------------
// RoPE cos/sin table
// ---------------------------------------------------------------------------
__global__ void sincos_kernel() {
    int idx = blockIdx.x * blockDim.x + threadIdx.x;
    if (idx >= SS * 32) return;
    int j = idx & 31;
    int s = idx >> 5;
    double invf = exp(-((double)j / 32.0) * log(10000.0));
    double a = (double)s * invf;
    g_cos[idx] = (float)cos(a);
    g_sin[idx] = (float)sin(a);
}

// ---------------------------------------------------------------------------
// Convert hidden states to fp16 (half2-packed)
// ---------------------------------------------------------------------------
__global__ __launch_bounds__(256) void round_xh(const float4* __restrict__ X) {
    int i = blockIdx.x * blockDim.x + threadIdx.x;   // uint4 index
    float4 a = X[2 * i], b = X[2 * i + 1];
    uint4 o;
    o.x = packh2(a.x, a.y);
    o.y = packh2(a.z, a.w);
    o.z = packh2(b.x, b.y);
    o.w = packh2(b.z, b.w);
    ((uint4*)g_Xh)[i] = o;
}

// ---------------------------------------------------------------------------
// Transpose + fp16-pack the three weight matrices: g_Wth[which][n][k]=W[k][n]
// ---------------------------------------------------------------------------
__global__ __launch_bounds__(256) void wt_transpose_h(
    const float* __restrict__ Wq,
    const float* __restrict__ Wk,
    const float* __restrict__ Wv)
{
    __shared__ float t[32][33];
    const float* W = (blockIdx.z == 0) ? Wq : (blockIdx.z == 1 ? Wk : Wv);
    unsigned* Out = g_Wth + (size_t)blockIdx.z * (HIDN * HIDN / 2);
    int k0 = blockIdx.x * 32, n0 = blockIdx.y * 32;
    int tx = threadIdx.x & 31, ty = threadIdx.x >> 5;   // 32 x 8
    #pragma unroll
    for (int p = 0; p < 4; p++) {
        int k = ty + p * 8;
        t[k][tx] = W[(k0 + k) * HIDN + n0 + tx];
    }
    __syncthreads();
    int nb = threadIdx.x >> 4;      // 0..15
    int kp = threadIdx.x & 15;      // k-pair 0..15
    #pragma unroll
    for (int p = 0; p < 2; p++) {
        int n = nb + p * 16;
        Out[(size_t)(n0 + n) * (HIDN / 2) + k0 / 2 + kp] =
            packh2(t[2 * kp][n], t[2 * kp + 1][n]);
    }
}

// ---------------------------------------------------------------------------
// Fused QKV projection GEMM — fp16 mma.m16n8k16 + ldmatrix + 4-stage cp.async.
// Block tile 128x128, 8 warps (2m x 4n), warp tile 64x32.
// K chunk = 32 halves (16 uint32/row), 40 chunks, 4 smem stages.
// Dynamic smem (uint32): A[c%4] at c%4*2560 (128 rows x 20), B at 10240+...
// Row stride 20 uint32 = 80B (cp16/ldmatrix phases conflict-free).
// ---------------------------------------------------------------------------
#define QKV_SMEM_BYTES (20480 * 4)

__global__ __launch_bounds__(256, 2) void qkv_gemm_fp16(
    const float* __restrict__ bq,
    const float* __restrict__ bk,
    const float* __restrict__ bv)
{
    extern __shared__ unsigned smu[];

    const int n0g   = blockIdx.x * 128;
    const int m0    = blockIdx.y * 128;
    const int which = n0g / HIDN;
    const int ncol0 = n0g % HIDN;

    const unsigned* Wp = g_Wth + (size_t)which * (HIDN * HIDN / 2);
    const float* bias  = (which == 0) ? bq : (which == 1 ? bk : bv);
    float*       Out   = (which == 0) ? g_Q : (which == 1 ? g_K : g_V);

    const int tid  = threadIdx.x;
    const int lane = tid & 31;
    const int warp = tid >> 5;
    const int wm   = (warp & 1) * 64;
    const int wn   = (warp >> 1) * 32;
    const int g    = lane >> 2;
    const int t4   = lane & 3;

    const unsigned int sbase = (unsigned int)__cvta_generic_to_shared(smu);
    const int st_row = tid & 127;        // staged row
    const int st_o   = (tid >> 7) * 8;   // 0 or 8 (each thread: 2 cp16/row)

    const unsigned a_loff =
        ((unsigned)((wm + (lane & 15)) * 20 + (lane >> 4) * 4)) * 4;
    const unsigned b_loff =
        ((unsigned)((wn + (lane >> 4) * 8 + (lane & 7)) * 20 +
                    ((lane >> 3) & 1) * 4)) * 4;

    float acc[4][4][4];
    #pragma unroll
    for (int mt = 0; mt < 4; mt++)
        #pragma unroll
        for (int nt = 0; nt < 4; nt++)
            #pragma unroll
            for (int i = 0; i < 4; i++) acc[mt][nt][i] = 0.0f;

    const unsigned* srcA = g_Xh + (size_t)(m0 + st_row) * (HIDN / 2);
    const unsigned* srcB = Wp + (size_t)(ncol0 + st_row) * (HIDN / 2);

    auto stage = [&](int c, int b) {
        const int dA = b * 2560 + st_row * 20 + st_o;
        const int dB = 10240 + b * 2560 + st_row * 20 + st_o;
        const int so = c * 16 + st_o;
        cp16(sbase + dA * 4,       srcA + so);
        cp16(sbase + (dA + 4) * 4, srcA + so + 4);
        cp16(sbase + dB * 4,       srcB + so);
        cp16(sbase + (dB + 4) * 4, srcB + so + 4);
    };

    // Prologue: stage chunks 0,1,2 into buffers 0,1,2 (3 groups)
    stage(0, 0); cp_commit();
    stage(1, 1); cp_commit();
    stage(2, 2); cp_commit();

    for (int kt = 0; kt < 40; kt++) {
        const int buf = kt & 3;
        cp_wait<2>();       // chunk kt landed (kt+1, kt+2 may be in flight)
        __syncthreads();    // all warps done with buffer (kt+3)%4's old chunk

        if (kt + 3 < 40) stage(kt + 3, (kt + 3) & 3);
        cp_commit();        // always commit (possibly empty) to keep counts

        const unsigned Abase = sbase + buf * 2560 * 4 + a_loff;
        const unsigned Bbase = sbase + (10240 + buf * 2560) * 4 + b_loff;

        #pragma unroll
        for (int s = 0; s < 2; s++) {        // 2 k16 steps per chunk
            unsigned a[4][4];
            #pragma unroll
            for (int mt = 0; mt < 4; mt++)
                ldm_x4(a[mt], Abase + (mt * 1280 + s * 32));
            unsigned bf[2][4];
            #pragma unroll
            for (int ntp = 0; ntp < 2; ntp++)
                ldm_x4(bf[ntp], Bbase + (ntp * 1280 + s * 32));
            #pragma unroll
            for (int nt = 0; nt < 4; nt++) {
                unsigned b0 = bf[nt >> 1][(nt & 1) * 2];
                unsigned b1 = bf[nt >> 1][(nt & 1) * 2 + 1];
                #pragma unroll
                for (int mt = 0; mt < 4; mt++)
                    mma_f16(acc[mt][nt], a[mt], b0, b1);
            }
        }
    }

    // Epilogue: bias + scatter into [B, H, S, D] (fp32)
    #pragma unroll
    for (int mt = 0; mt < 4; mt++) {
        #pragma unroll
        for (int nt = 0; nt < 4; nt++) {
            int col = ncol0 + wn + nt * 8 + t4 * 2;
            int h = col >> 6;
            int d = col & 63;
            float bi0 = bias[col];
            float bi1 = bias[col + 1];
            #pragma unroll
            for (int rh = 0; rh < 2; rh++) {
                int m = m0 + wm + mt * 16 + g + rh * 8;
                int b = m >> 11;
                int s = m & 2047;
                float2 v;
                v.x = acc[mt][nt][rh * 2 + 0] + bi0;
                v.y = acc[mt][nt][rh * 2 + 1] + bi1;
                *(float2*)&Out[(((b * NH + h) * SS) + s) * HD + d] = v;
            }
        }
    }
}

// ---------------------------------------------------------------------------
// Fused rope + pack: per (bh, 32-row tile):
//   Q: rope + scale -> g_Qh (fp16 packed)
//   K: rope -> smem -> repack -> g_Kf (fp16, per-lane B-frag order)
//   V: -> smem -> repack -> g_Vf
// ---------------------------------------------------------------------------
__global__ __launch_bounds__(256) void rope_pack() {
    __shared__ float Ks[32][68];
    __shared__ float Vs[32][68];

    const int tile = blockIdx.x;          // 0..63
    const int bh   = blockIdx.y;          // 0..39
    const size_t tbase = ((size_t)bh * SS + tile * 32) * HD;
    const float* Qb = g_Q + tbase;
    const float* Kb = g_K + tbase;
    const float* Vb = g_V + tbase;

    const int t   = threadIdx.x;
    const int row = t >> 3;               // 0..31
    const int c   = (t & 7) * 4;          // 0..28
    const int s   = tile * 32 + row;
    const float scale = 0.125f;

    float4 cs = *(const float4*)&g_cos[(s << 5) + c];
    float4 sn = *(const float4*)&g_sin[(s << 5) + c];

    // K rope -> smem
    {
        float4 k1 = *(const float4*)&Kb[row * HD + c];
        float4 k2 = *(const float4*)&Kb[row * HD + c + 32];
        Ks[row][c + 0]  = k1.x * cs.x - k2.x * sn.x;
        Ks[row][c + 1]  = k1.y * cs.y - k2.y * sn.y;
        Ks[row][c + 2]  = k1.z * cs.z - k2.z * sn.z;
        Ks[row][c + 3]  = k1.w * cs.w - k2.w * sn.w;
        Ks[row][c + 32] = k2.x * cs.x + k1.x * sn.x;
        Ks[row][c + 33] = k2.y * cs.y + k1.y * sn.y;
        Ks[row][c + 34] = k2.z * cs.z + k1.z * sn.z;
        Ks[row][c + 35] = k2.w * cs.w + k1.w * sn.w;
    }
    // V straight -> smem
    {
        float4 v1 = *(const float4*)&Vb[row * HD + c];
        float4 v2 = *(const float4*)&Vb[row * HD + c + 32];
        *(float4*)&Vs[row][c]      = v1;
        *(float4*)&Vs[row][c + 32] = v2;
    }
    // Q rope + scale -> g_Qh directly
    {
        float4 q1 = *(const float4*)&Qb[row * HD + c];
        float4 q2 = *(const float4*)&Qb[row * HD + c + 32];
        uint2 lo, hi;
        lo.x = packh2((q1.x * cs.x - q2.x * sn.x) * scale,
                      (q1.y * cs.y - q2.y * sn.y) * scale);
        lo.y = packh2((q1.z * cs.z - q2.z * sn.z) * scale,
                      (q1.w * cs.w - q2.w * sn.w) * scale);
        hi.x = packh2((q2.x * cs.x + q1.x * sn.x) * scale,
                      (q2.y * cs.y + q1.y * sn.y) * scale);
        hi.y = packh2((q2.z * cs.z + q1.z * sn.z) * scale,
                      (q2.w * cs.w + q1.w * sn.w) * scale);
        unsigned qb = (unsigned)((bh * SS + s) * 32);
        *(uint2*)&g_Qh[qb + c / 2]      = lo;
        *(uint2*)&g_Qh[qb + 16 + c / 2] = hi;
    }
    __syncthreads();

    // Repack K/V to per-lane mma B-fragment order (fp16)
    const int lane = t >> 3;              // 0..31
    const int q    = t & 7;               // handles vi = 4q..4q+3
    const int g    = lane >> 2;
    const int t4   = lane & 3;
    const size_t rowidx = (((size_t)bh * 64 + tile) * 32 + lane);

    unsigned ok[4], ov[4];
    #pragma unroll
    for (int i = 0; i < 4; i++) {
        int vi = q * 4 + i;
        int nt = vi >> 3, r = vi & 7, kc = r >> 1, b = r & 1;
        int d0 = 2 * t4 + 16 * kc + 8 * b;
        ok[i] = packh2(Ks[nt * 8 + g][d0], Ks[nt * 8 + g][d0 + 1]);
        int dt = vi >> 2, r2 = vi & 3, sx = r2 >> 1, bv = r2 & 1;
        int k0 = 2 * t4 + 16 * sx + 8 * bv;
        ov[i] = packh2(Vs[k0][dt * 8 + g], Vs[k0 + 1][dt * 8 + g]);
    }
    ((uint4*)g_Kf)[rowidx * 8 + q] = *(uint4*)&ok[0];
    ((uint4*)g_Vf)[rowidx * 8 + q] = *(uint4*)&ov[0];
}

// ---------------------------------------------------------------------------
// Flash attention, fp16 mma.m16n8k16, BKV=64 (two prepacked 32-key subtiles
// per buffer, one barrier pair per 64 keys), cp.async double-buffered.
// Dynamic smem (uint32):
//   [0,    2304)  Qs2[64][36] staging; overlaid Ps2[64][20]
//   [2304, 6912)  K buf0/buf1, each 2304 (2 subtiles x 32 lanes x 36)
//   [6912, 11520) V buf0/buf1
// ---------------------------------------------------------------------------
#define AOFF_K 2304
#define AOFF_V 6912
#define ABUF 2304
#define ASUB 1152
#define ATTN_SMEM_BYTES (11520 * 4)

__global__ __launch_bounds__(128) void attn_fp16(
    const float* __restrict__ mask, float* __restrict__ out)
{
    extern __shared__ unsigned smu[];

    const int bh = blockIdx.y;
    const int b  = bh / NH;
    const int h  = bh % NH;
    const int q0 = blockIdx.x * 64;

    const unsigned* Qhb = g_Qh + (size_t)(bh * SS + q0) * 32;
    const unsigned* Kfb = g_Kf + (size_t)bh * 65536;
    const unsigned* Vfb = g_Vf + (size_t)bh * 65536;
    const float2* mk2 = (const float2*)(mask + b * SS);

    const int tid  = threadIdx.x;
    const int lane = tid & 31;
    const int warp = tid >> 5;
    const int g    = lane >> 2;
    const int t4   = lane & 3;
    const int wm   = warp * 16;

    const unsigned int sbase = (unsigned int)__cvta_generic_to_shared(smu);
    const int c_lane = tid >> 2;
    const int c_seg  = tid & 3;

    auto stage_kv = [&](int it, int buf) {   // stage tiles 2it, 2it+1
        #pragma unroll
        for (int sub = 0; sub < 2; sub++) {
            const unsigned* Kt = Kfb + (2 * it + sub) * 1024 + c_lane * 32;
            const unsigned* Vt = Vfb + (2 * it + sub) * 1024 + c_lane * 32;
            int dK = AOFF_K + buf * ABUF + sub * ASUB + c_lane * 36;
            int dV = AOFF_V + buf * ABUF + sub * ASUB + c_lane * 36;
            #pragma unroll
            for (int u = 0; u < 2; u++) {
                int o = c_seg * 8 + u * 4;
                cp16(sbase + (dK + o) * 4, Kt + o);
                cp16(sbase + (dV + o) * 4, Vt + o);
            }
        }
    };

    stage_kv(0, 0);
    cp_commit();

    // Stage Q (64 rows x 32 uint32)
    for (int i = tid; i < 512; i += 128) {
        int row = i >> 3, c4 = (i & 7) * 4;
        *(uint4*)&smu[row * 36 + c4] = ((const uint4*)Qhb)[i];
    }
    __syncthreads();

    unsigned qf[4][4];
    #pragma unroll
    for (int kc = 0; kc < 4; kc++) {
        qf[kc][0] = smu[(wm + g    ) * 36 + kc * 8 + t4    ];
        qf[kc][1] = smu[(wm + g + 8) * 36 + kc * 8 + t4    ];
        qf[kc][2] = smu[(wm + g    ) * 36 + kc * 8 + t4 + 4];
        qf[kc][3] = smu[(wm + g + 8) * 36 + kc * 8 + t4 + 4];
    }

    float oacc[8][4];
    #pragma unroll
    for (int dt = 0; dt < 8; dt++)
        #pragma unroll
        for (int i = 0; i < 4; i++) oacc[dt][i] = 0.0f;
    float m0r = -1e30f, m1r = -1e30f, l0 = 0.0f, l1 = 0.0f;

    for (int it = 0; it < SS / 64; it++) {
        const int buf = it & 1;
        cp_wait<0>();
        __syncthreads();   // buf visible + all done reading buf^1

        if (it < SS / 64 - 1) {
            stage_kv(it + 1, buf ^ 1);
            cp_commit();
        }

        #pragma unroll
        for (int sub = 0; sub < 2; sub++) {
            const uint4* K4 = (const uint4*)(smu + AOFF_K + buf * ABUF + sub * ASUB);
            const uint4* V4 = (const uint4*)(smu + AOFF_V + buf * ABUF + sub * ASUB);
            const int lb = lane * 9;

            // ---- S = Q @ K^T ----
            float sc[4][4];
            #pragma unroll
            for (int nt = 0; nt < 4; nt++)
                #pragma unroll
                for (int i = 0; i < 4; i++) sc[nt][i] = 0.0f;

            #pragma unroll
            for (int nt = 0; nt < 4; nt++) {
                unsigned kf[8];
                *(uint4*)&kf[0] = K4[lb + nt * 2];
                *(uint4*)&kf[4] = K4[lb + nt * 2 + 1];
                #pragma unroll
                for (int kc = 0; kc < 4; kc++)
                    mma_f16(sc[nt], qf[kc], kf[kc * 2], kf[kc * 2 + 1]);
            }

            // ---- mask + online softmax ----
            const int k0 = it * 64 + sub * 32;
            #pragma unroll
            for (int nt = 0; nt < 4; nt++) {
                float2 mv = __ldg(&mk2[(k0 + nt * 8) / 2 + t4]);
                sc[nt][0] += mv.x; sc[nt][1] += mv.y;
                sc[nt][2] += mv.x; sc[nt][3] += mv.y;
            }
            float rx0 = -1e30f, rx1 = -1e30f;
            #pragma unroll
            for (int nt = 0; nt < 4; nt++) {
                rx0 = fmaxf(rx0, fmaxf(sc[nt][0], sc[nt][1]));
                rx1 = fmaxf(rx1, fmaxf(sc[nt][2], sc[nt][3]));
            }
            rx0 = fmaxf(rx0, __shfl_xor_sync(0xffffffffu, rx0, 1));
            rx0 = fmaxf(rx0, __shfl_xor_sync(0xffffffffu, rx0, 2));
            rx1 = fmaxf(rx1, __shfl_xor_sync(0xffffffffu, rx1, 1));
            rx1 = fmaxf(rx1, __shfl_xor_sync(0xffffffffu, rx1, 2));

            float m0n = fmaxf(m0r, rx0);
            float m1n = fmaxf(m1r, rx1);
            float c0 = __expf(m0r - m0n);
            float c1 = __expf(m1r - m1n);
            m0r = m0n; m1r = m1n;

            float rs0 = 0.0f, rs1 = 0.0f;
            #pragma unroll
            for (int nt = 0; nt < 4; nt++) {
                float p0 = __expf(sc[nt][0] - m0n);
                float p1 = __expf(sc[nt][1] - m0n);
                float p2 = __expf(sc[nt][2] - m1n);
                float p3 = __expf(sc[nt][3] - m1n);
                unsigned h01 = packh2(p0, p1);
                unsigned h23 = packh2(p2, p3);
                float2 f01 = __half22float2(*(__half2*)&h01);
                float2 f23 = __half22float2(*(__half2*)&h23);
                rs0 += f01.x + f01.y;
                rs1 += f23.x + f23.y;
                smu[(wm + g    ) * 20 + nt * 4 + t4] = h01;
                smu[(wm + g + 8) * 20 + nt * 4 + t4] = h23;
            }
            rs0 += __shfl_xor_sync(0xffffffffu, rs0, 1);
            rs0 += __shfl_xor_sync(0xffffffffu, rs0, 2);
            rs1 += __shfl_xor_sync(0xffffffffu, rs1, 1);
            rs1 += __shfl_xor_sync(0xffffffffu, rs1, 2);
            l0 = l0 * c0 + rs0;
            l1 = l1 * c1 + rs1;

            #pragma unroll
            for (int dt = 0; dt < 8; dt++) {
                oacc[dt][0] *= c0; oacc[dt][1] *= c0;
                oacc[dt][2] *= c1; oacc[dt][3] *= c1;
            }
            __syncwarp();   // Ps rows are warp-private

            // ---- O += P @ V ----
            unsigned pa[2][4];
            #pragma unroll
            for (int s = 0; s < 2; s++) {
                pa[s][0] = smu[(wm + g    ) * 20 + s * 8 + t4    ];
                pa[s][1] = smu[(wm + g + 8) * 20 + s * 8 + t4    ];
                pa[s][2] = smu[(wm + g    ) * 20 + s * 8 + t4 + 4];
                pa[s][3] = smu[(wm + g + 8) * 20 + s * 8 + t4 + 4];
            }
            #pragma unroll
            for (int dt = 0; dt < 8; dt++) {
                unsigned vf[4];
                *(uint4*)&vf[0] = V4[lb + dt];
                mma_f16(oacc[dt], pa[0], vf[0], vf[1]);
                mma_f16(oacc[dt], pa[1], vf[2], vf[3]);
            }
            __syncwarp();   // Ps reads done before next subtile overwrites
        }
    }

    float inv0 = 1.0f / l0;
    float inv1 = 1.0f / l1;
    int r0 = q0 + wm + g;
    int r1 = r0 + 8;
    #pragma unroll
    for (int dt = 0; dt < 8; dt++) {
        int d = dt * 8 + 2 * t4;
        float2 v0 = make_float2(oacc[dt][0] * inv0, oacc[dt][1] * inv0);
        float2 v1 = make_float2(oacc[dt][2] * inv1, oacc[dt][3] * inv1);
        *(float2*)&out[(b * SS + r0) * HIDN + h * HD + d] = v0;
        *(float2*)&out[(b * SS + r1) * HIDN + h * HD + d] = v1;
    }
}

// ---------------------------------------------------------------------------
extern "C" void kernel_launch(void* const* d_in, const int* in_sizes, int n_in,
                              void* d_out, int out_size) {
    const float* hs   = (const float*)d_in[0];
    const float* mask = (const float*)d_in[1];
    const float* Wq   = (const float*)d_in[2];
    const float* bq   = (const float*)d_in[3];
    const float* Wk   = (const float*)d_in[4];
    const float* bk   = (const float*)d_in[5];
    const float* Wv   = (const float*)d_in[6];
    const float* bv   = (const float*)d_in[7];
    float* out = (float*)d_out;

    static bool attr_set = false;
    if (!attr_set) {
        cudaFuncSetAttribute(qkv_gemm_fp16,
                             cudaFuncAttributeMaxDynamicSharedMemorySize,
                             QKV_SMEM_BYTES);
        cudaFuncSetAttribute(attn_fp16,
                             cudaFuncAttributeMaxDynamicSharedMemorySize,
                             ATTN_SMEM_BYTES);
        attr_set = true;
    }

    sincos_kernel<<<(SS * 32 + 255) / 256, 256>>>();
    round_xh<<<(BB * SS * HIDN / 8) / 256, 256>>>((const float4*)hs);
    wt_transpose_h<<<dim3(HIDN / 32, HIDN / 32, 3), 256>>>(Wq, Wk, Wv);
    qkv_gemm_fp16<<<dim3(30, 32), 256, QKV_SMEM_BYTES>>>(bq, bk, bv);
    rope_pack<<<dim3(SS / 32, BB * NH), 256>>>();
    attn_fp16<<<dim3(SS / 64, BB * NH), 128, ATTN_SMEM_BYTES>>>(mask, out);
}

// round 14
// speedup vs baseline: 1.0592x; 1.0592x over previous
#include <cuda_runtime.h>
#include <cuda_fp16.h>
#include <cstdint>
#include <math.h>

#define BB 2
#define SS 2048
#define HIDN 1280
#define NH 20
#define HD 64

// Scratch (alloc-free rule: __device__ globals)
__device__ float g_Q[BB*NH*SS*HD];
__device__ float g_K[BB*NH*SS*HD];
__device__ float g_V[BB*NH*SS*HD];
__device__ unsigned g_Qh[BB*NH*SS*HD/2];     // Q fp16 (half2-packed along d)
__device__ unsigned g_Kf[BB*NH*SS*HD/2];     // K fp16, per-lane mma B-frag order
__device__ unsigned g_Vf[BB*NH*SS*HD/2];     // V fp16, per-lane mma B-frag order
__device__ unsigned g_Xh[BB*SS*HIDN/2];      // hidden states fp16
__device__ unsigned g_Wth[3*HIDN*HIDN/2];    // transposed weights fp16 ([n][k])
__device__ float g_cos[SS*32];
__device__ float g_sin[SS*32];

// ---------------------------------------------------------------------------
// helpers
// ---------------------------------------------------------------------------
__device__ __forceinline__ unsigned packh2(float x, float y) {
    __half2 h = __floats2half2_rn(x, y);
    return *reinterpret_cast<unsigned*>(&h);
}

__device__ __forceinline__ void mma_f16(float c[4], const unsigned a[4],
                                        unsigned b0, unsigned b1) {
    asm volatile(
        "mma.sync.aligned.m16n8k16.row.col.f32.f16.f16.f32 "
        "{%0,%1,%2,%3}, {%4,%5,%6,%7}, {%8,%9}, {%0,%1,%2,%3};"
        : "+f"(c[0]), "+f"(c[1]), "+f"(c[2]), "+f"(c[3])
        : "r"(a[0]), "r"(a[1]), "r"(a[2]), "r"(a[3]),
          "r"(b0), "r"(b1));
}

__device__ __forceinline__ void ldm_x4(unsigned r[4], unsigned addr) {
    asm volatile(
        "ldmatrix.sync.aligned.m8n8.x4.shared.b16 {%0,%1,%2,%3}, [%4];"
        : "=r"(r[0]), "=r"(r[1]), "=r"(r[2]), "=r"(r[3])
        : "r"(addr));
}

__device__ __forceinline__ void cp16(unsigned int dst, const void* src) {
    asm volatile("cp.async.cg.shared.global [%0], [%1], 16;\n"
                 :: "r"(dst), "l"(src));
}
__device__ __forceinline__ void cp_commit() {
    asm volatile("cp.async.commit_group;\n" ::: "memory");
}
template <int N>
__device__ __forceinline__ void cp_wait() {
    asm volatile("cp.async.wait_group %0;\n" :: "n"(N) : "memory");
}

// ---------------------------------------------------------------------------
// RoPE cos/sin table
// ---------------------------------------------------------------------------
__global__ void sincos_kernel() {
    int idx = blockIdx.x * blockDim.x + threadIdx.x;
    if (idx >= SS * 32) return;
    int j = idx & 31;
    int s = idx >> 5;
    double invf = exp(-((double)j / 32.0) * log(10000.0));
    double a = (double)s * invf;
    g_cos[idx] = (float)cos(a);
    g_sin[idx] = (float)sin(a);
}

// ---------------------------------------------------------------------------
// Convert hidden states to fp16 (half2-packed)
// ---------------------------------------------------------------------------
__global__ __launch_bounds__(256) void round_xh(const float4* __restrict__ X) {
    int i = blockIdx.x * blockDim.x + threadIdx.x;   // uint4 index
    float4 a = X[2 * i], b = X[2 * i + 1];
    uint4 o;
    o.x = packh2(a.x, a.y);
    o.y = packh2(a.z, a.w);
    o.z = packh2(b.x, b.y);
    o.w = packh2(b.z, b.w);
    ((uint4*)g_Xh)[i] = o;
}

// ---------------------------------------------------------------------------
// Transpose + fp16-pack the three weight matrices: g_Wth[which][n][k]=W[k][n]
// ---------------------------------------------------------------------------
__global__ __launch_bounds__(256) void wt_transpose_h(
    const float* __restrict__ Wq,
    const float* __restrict__ Wk,
    const float* __restrict__ Wv)
{
    __shared__ float t[32][33];
    const float* W = (blockIdx.z == 0) ? Wq : (blockIdx.z == 1 ? Wk : Wv);
    unsigned* Out = g_Wth + (size_t)blockIdx.z * (HIDN * HIDN / 2);
    int k0 = blockIdx.x * 32, n0 = blockIdx.y * 32;
    int tx = threadIdx.x & 31, ty = threadIdx.x >> 5;   // 32 x 8
    #pragma unroll
    for (int p = 0; p < 4; p++) {
        int k = ty + p * 8;
        t[k][tx] = W[(k0 + k) * HIDN + n0 + tx];
    }
    __syncthreads();
    int nb = threadIdx.x >> 4;      // 0..15
    int kp = threadIdx.x & 15;      // k-pair 0..15
    #pragma unroll
    for (int p = 0; p < 2; p++) {
        int n = nb + p * 16;
        Out[(size_t)(n0 + n) * (HIDN / 2) + k0 / 2 + kp] =
            packh2(t[2 * kp][n], t[2 * kp + 1][n]);
    }
}

// ---------------------------------------------------------------------------
// Fused QKV projection GEMM — fp16 mma.m16n8k16 + ldmatrix + 4-stage cp.async.
// (unchanged from R13: measured 196 us)
// ---------------------------------------------------------------------------
#define QKV_SMEM_BYTES (20480 * 4)

__global__ __launch_bounds__(256, 2) void qkv_gemm_fp16(
    const float* __restrict__ bq,
    const float* __restrict__ bk,
    const float* __restrict__ bv)
{
    extern __shared__ unsigned smu[];

    const int n0g   = blockIdx.x * 128;
    const int m0    = blockIdx.y * 128;
    const int which = n0g / HIDN;
    const int ncol0 = n0g % HIDN;

    const unsigned* Wp = g_Wth + (size_t)which * (HIDN * HIDN / 2);
    const float* bias  = (which == 0) ? bq : (which == 1 ? bk : bv);
    float*       Out   = (which == 0) ? g_Q : (which == 1 ? g_K : g_V);

    const int tid  = threadIdx.x;
    const int lane = tid & 31;
    const int warp = tid >> 5;
    const int wm   = (warp & 1) * 64;
    const int wn   = (warp >> 1) * 32;
    const int g    = lane >> 2;
    const int t4   = lane & 3;

    const unsigned int sbase = (unsigned int)__cvta_generic_to_shared(smu);
    const int st_row = tid & 127;
    const int st_o   = (tid >> 7) * 8;

    const unsigned a_loff =
        ((unsigned)((wm + (lane & 15)) * 20 + (lane >> 4) * 4)) * 4;
    const unsigned b_loff =
        ((unsigned)((wn + (lane >> 4) * 8 + (lane & 7)) * 20 +
                    ((lane >> 3) & 1) * 4)) * 4;

    float acc[4][4][4];
    #pragma unroll
    for (int mt = 0; mt < 4; mt++)
        #pragma unroll
        for (int nt = 0; nt < 4; nt++)
            #pragma unroll
            for (int i = 0; i < 4; i++) acc[mt][nt][i] = 0.0f;

    const unsigned* srcA = g_Xh + (size_t)(m0 + st_row) * (HIDN / 2);
    const unsigned* srcB = Wp + (size_t)(ncol0 + st_row) * (HIDN / 2);

    auto stage = [&](int c, int b) {
        const int dA = b * 2560 + st_row * 20 + st_o;
        const int dB = 10240 + b * 2560 + st_row * 20 + st_o;
        const int so = c * 16 + st_o;
        cp16(sbase + dA * 4,       srcA + so);
        cp16(sbase + (dA + 4) * 4, srcA + so + 4);
        cp16(sbase + dB * 4,       srcB + so);
        cp16(sbase + (dB + 4) * 4, srcB + so + 4);
    };

    stage(0, 0); cp_commit();
    stage(1, 1); cp_commit();
    stage(2, 2); cp_commit();

    for (int kt = 0; kt < 40; kt++) {
        const int buf = kt & 3;
        cp_wait<2>();
        __syncthreads();

        if (kt + 3 < 40) stage(kt + 3, (kt + 3) & 3);
        cp_commit();

        const unsigned Abase = sbase + buf * 2560 * 4 + a_loff;
        const unsigned Bbase = sbase + (10240 + buf * 2560) * 4 + b_loff;

        #pragma unroll
        for (int s = 0; s < 2; s++) {
            unsigned a[4][4];
            #pragma unroll
            for (int mt = 0; mt < 4; mt++)
                ldm_x4(a[mt], Abase + (mt * 1280 + s * 32));
            unsigned bf[2][4];
            #pragma unroll
            for (int ntp = 0; ntp < 2; ntp++)
                ldm_x4(bf[ntp], Bbase + (ntp * 1280 + s * 32));
            #pragma unroll
            for (int nt = 0; nt < 4; nt++) {
                unsigned b0 = bf[nt >> 1][(nt & 1) * 2];
                unsigned b1 = bf[nt >> 1][(nt & 1) * 2 + 1];
                #pragma unroll
                for (int mt = 0; mt < 4; mt++)
                    mma_f16(acc[mt][nt], a[mt], b0, b1);
            }
        }
    }

    #pragma unroll
    for (int mt = 0; mt < 4; mt++) {
        #pragma unroll
        for (int nt = 0; nt < 4; nt++) {
            int col = ncol0 + wn + nt * 8 + t4 * 2;
            int h = col >> 6;
            int d = col & 63;
            float bi0 = bias[col];
            float bi1 = bias[col + 1];
            #pragma unroll
            for (int rh = 0; rh < 2; rh++) {
                int m = m0 + wm + mt * 16 + g + rh * 8;
                int b = m >> 11;
                int s = m & 2047;
                float2 v;
                v.x = acc[mt][nt][rh * 2 + 0] + bi0;
                v.y = acc[mt][nt][rh * 2 + 1] + bi1;
                *(float2*)&Out[(((b * NH + h) * SS) + s) * HD + d] = v;
            }
        }
    }
}

// ---------------------------------------------------------------------------
// Fused rope + pack (unchanged from R13).
// ---------------------------------------------------------------------------
__global__ __launch_bounds__(256) void rope_pack() {
    __shared__ float Ks[32][68];
    __shared__ float Vs[32][68];

    const int tile = blockIdx.x;
    const int bh   = blockIdx.y;
    const size_t tbase = ((size_t)bh * SS + tile * 32) * HD;
    const float* Qb = g_Q + tbase;
    const float* Kb = g_K + tbase;
    const float* Vb = g_V + tbase;

    const int t   = threadIdx.x;
    const int row = t >> 3;
    const int c   = (t & 7) * 4;
    const int s   = tile * 32 + row;
    const float scale = 0.125f;

    float4 cs = *(const float4*)&g_cos[(s << 5) + c];
    float4 sn = *(const float4*)&g_sin[(s << 5) + c];

    {
        float4 k1 = *(const float4*)&Kb[row * HD + c];
        float4 k2 = *(const float4*)&Kb[row * HD + c + 32];
        Ks[row][c + 0]  = k1.x * cs.x - k2.x * sn.x;
        Ks[row][c + 1]  = k1.y * cs.y - k2.y * sn.y;
        Ks[row][c + 2]  = k1.z * cs.z - k2.z * sn.z;
        Ks[row][c + 3]  = k1.w * cs.w - k2.w * sn.w;
        Ks[row][c + 32] = k2.x * cs.x + k1.x * sn.x;
        Ks[row][c + 33] = k2.y * cs.y + k1.y * sn.y;
        Ks[row][c + 34] = k2.z * cs.z + k1.z * sn.z;
        Ks[row][c + 35] = k2.w * cs.w + k1.w * sn.w;
    }
    {
        float4 v1 = *(const float4*)&Vb[row * HD + c];
        float4 v2 = *(const float4*)&Vb[row * HD + c + 32];
        *(float4*)&Vs[row][c]      = v1;
        *(float4*)&Vs[row][c + 32] = v2;
    }
    {
        float4 q1 = *(const float4*)&Qb[row * HD + c];
        float4 q2 = *(const float4*)&Qb[row * HD + c + 32];
        uint2 lo, hi;
        lo.x = packh2((q1.x * cs.x - q2.x * sn.x) * scale,
                      (q1.y * cs.y - q2.y * sn.y) * scale);
        lo.y = packh2((q1.z * cs.z - q2.z * sn.z) * scale,
                      (q1.w * cs.w - q2.w * sn.w) * scale);
        hi.x = packh2((q2.x * cs.x + q1.x * sn.x) * scale,
                      (q2.y * cs.y + q1.y * sn.y) * scale);
        hi.y = packh2((q2.z * cs.z + q1.z * sn.z) * scale,
                      (q2.w * cs.w + q1.w * sn.w) * scale);
        unsigned qb = (unsigned)((bh * SS + s) * 32);
        *(uint2*)&g_Qh[qb + c / 2]      = lo;
        *(uint2*)&g_Qh[qb + 16 + c / 2] = hi;
    }
    __syncthreads();

    const int lane = t >> 3;
    const int q    = t & 7;
    const int g    = lane >> 2;
    const int t4   = lane & 3;
    const size_t rowidx = (((size_t)bh * 64 + tile) * 32 + lane);

    unsigned ok[4], ov[4];
    #pragma unroll
    for (int i = 0; i < 4; i++) {
        int vi = q * 4 + i;
        int nt = vi >> 3, r = vi & 7, kc = r >> 1, b = r & 1;
        int d0 = 2 * t4 + 16 * kc + 8 * b;
        ok[i] = packh2(Ks[nt * 8 + g][d0], Ks[nt * 8 + g][d0 + 1]);
        int dt = vi >> 2, r2 = vi & 3, sx = r2 >> 1, bv = r2 & 1;
        int k0 = 2 * t4 + 16 * sx + 8 * bv;
        ov[i] = packh2(Vs[k0][dt * 8 + g], Vs[k0 + 1][dt * 8 + g]);
    }
    ((uint4*)g_Kf)[rowidx * 8 + q] = *(uint4*)&ok[0];
    ((uint4*)g_Vf)[rowidx * 8 + q] = *(uint4*)&ov[0];
}

// ---------------------------------------------------------------------------
// Flash attention, fp16 mma.m16n8k16, BKV=32 (exact R12 version — measured
// as part of the 475.9 us total).
// ---------------------------------------------------------------------------
#define AOFF_K 2304
#define AOFF_V 4608
#define ABUF 1152
#define ATTN_SMEM_BYTES (6912 * 4)

__global__ __launch_bounds__(128) void attn_fp16(
    const float* __restrict__ mask, float* __restrict__ out)
{
    extern __shared__ unsigned smu[];

    const int bh = blockIdx.y;
    const int b  = bh / NH;
    const int h  = bh % NH;
    const int q0 = blockIdx.x * 64;

    const unsigned* Qhb = g_Qh + (size_t)(bh * SS + q0) * 32;
    const unsigned* Kfb = g_Kf + (size_t)bh * 65536;
    const unsigned* Vfb = g_Vf + (size_t)bh * 65536;
    const float2* mk2 = (const float2*)(mask + b * SS);

    const int tid  = threadIdx.x;
    const int lane = tid & 31;
    const int warp = tid >> 5;
    const int g    = lane >> 2;
    const int t4   = lane & 3;
    const int wm   = warp * 16;

    const unsigned int sbase = (unsigned int)__cvta_generic_to_shared(smu);
    const int c_lane = tid >> 2;
    const int c_seg  = tid & 3;

    {
        #pragma unroll
        for (int u = 0; u < 2; u++) {
            int o = c_seg * 8 + u * 4;
            cp16(sbase + (AOFF_K + c_lane * 36 + o) * 4, Kfb + c_lane * 32 + o);
            cp16(sbase + (AOFF_V + c_lane * 36 + o) * 4, Vfb + c_lane * 32 + o);
        }
        cp_commit();
    }

    for (int i = tid; i < 512; i += 128) {
        int row = i >> 3, c4 = (i & 7) * 4;
        *(uint4*)&smu[row * 36 + c4] = ((const uint4*)Qhb)[i];
    }
    __syncthreads();

    unsigned qf[4][4];
    #pragma unroll
    for (int kc = 0; kc < 4; kc++) {
        qf[kc][0] = smu[(wm + g    ) * 36 + kc * 8 + t4    ];
        qf[kc][1] = smu[(wm + g + 8) * 36 + kc * 8 + t4    ];
        qf[kc][2] = smu[(wm + g    ) * 36 + kc * 8 + t4 + 4];
        qf[kc][3] = smu[(wm + g + 8) * 36 + kc * 8 + t4 + 4];
    }

    float oacc[8][4];
    #pragma unroll
    for (int dt = 0; dt < 8; dt++)
        #pragma unroll
        for (int i = 0; i < 4; i++) oacc[dt][i] = 0.0f;
    float m0r = -1e30f, m1r = -1e30f, l0 = 0.0f, l1 = 0.0f;

    for (int it = 0; it < SS / 32; it++) {
        const int buf = it & 1;
        cp_wait<0>();
        __syncthreads();

        if (it < SS / 32 - 1) {
            const unsigned* Kn = Kfb + (it + 1) * 1024;
            const unsigned* Vn = Vfb + (it + 1) * 1024;
            int ko = AOFF_K + (buf ^ 1) * ABUF;
            int vo = AOFF_V + (buf ^ 1) * ABUF;
            #pragma unroll
            for (int u = 0; u < 2; u++) {
                int o = c_seg * 8 + u * 4;
                cp16(sbase + (ko + c_lane * 36 + o) * 4, Kn + c_lane * 32 + o);
                cp16(sbase + (vo + c_lane * 36 + o) * 4, Vn + c_lane * 32 + o);
            }
            cp_commit();
        }

        const uint4* K4 = (const uint4*)(smu + AOFF_K + buf * ABUF);
        const uint4* V4 = (const uint4*)(smu + AOFF_V + buf * ABUF);
        const int lb = lane * 9;

        float sc[4][4];
        #pragma unroll
        for (int nt = 0; nt < 4; nt++)
            #pragma unroll
            for (int i = 0; i < 4; i++) sc[nt][i] = 0.0f;

        #pragma unroll
        for (int nt = 0; nt < 4; nt++) {
            unsigned kf[8];
            *(uint4*)&kf[0] = K4[lb + nt * 2];
            *(uint4*)&kf[4] = K4[lb + nt * 2 + 1];
            #pragma unroll
            for (int kc = 0; kc < 4; kc++)
                mma_f16(sc[nt], qf[kc], kf[kc * 2], kf[kc * 2 + 1]);
        }

        const int k0 = it * 32;
        #pragma unroll
        for (int nt = 0; nt < 4; nt++) {
            float2 mv = __ldg(&mk2[(k0 + nt * 8) / 2 + t4]);
            sc[nt][0] += mv.x; sc[nt][1] += mv.y;
            sc[nt][2] += mv.x; sc[nt][3] += mv.y;
        }
        float rx0 = -1e30f, rx1 = -1e30f;
        #pragma unroll
        for (int nt = 0; nt < 4; nt++) {
            rx0 = fmaxf(rx0, fmaxf(sc[nt][0], sc[nt][1]));
            rx1 = fmaxf(rx1, fmaxf(sc[nt][2], sc[nt][3]));
        }
        rx0 = fmaxf(rx0, __shfl_xor_sync(0xffffffffu, rx0, 1));
        rx0 = fmaxf(rx0, __shfl_xor_sync(0xffffffffu, rx0, 2));
        rx1 = fmaxf(rx1, __shfl_xor_sync(0xffffffffu, rx1, 1));
        rx1 = fmaxf(rx1, __shfl_xor_sync(0xffffffffu, rx1, 2));

        float m0n = fmaxf(m0r, rx0);
        float m1n = fmaxf(m1r, rx1);
        float c0 = __expf(m0r - m0n);
        float c1 = __expf(m1r - m1n);
        m0r = m0n; m1r = m1n;

        float rs0 = 0.0f, rs1 = 0.0f;
        #pragma unroll
        for (int nt = 0; nt < 4; nt++) {
            float p0 = __expf(sc[nt][0] - m0n);
            float p1 = __expf(sc[nt][1] - m0n);
            float p2 = __expf(sc[nt][2] - m1n);
            float p3 = __expf(sc[nt][3] - m1n);
            unsigned h01 = packh2(p0, p1);
            unsigned h23 = packh2(p2, p3);
            float2 f01 = __half22float2(*(__half2*)&h01);
            float2 f23 = __half22float2(*(__half2*)&h23);
            rs0 += f01.x + f01.y;
            rs1 += f23.x + f23.y;
            smu[(wm + g    ) * 20 + nt * 4 + t4] = h01;
            smu[(wm + g + 8) * 20 + nt * 4 + t4] = h23;
        }
        rs0 += __shfl_xor_sync(0xffffffffu, rs0, 1);
        rs0 += __shfl_xor_sync(0xffffffffu, rs0, 2);
        rs1 += __shfl_xor_sync(0xffffffffu, rs1, 1);
        rs1 += __shfl_xor_sync(0xffffffffu, rs1, 2);
        l0 = l0 * c0 + rs0;
        l1 = l1 * c1 + rs1;

        #pragma unroll
        for (int dt = 0; dt < 8; dt++) {
            oacc[dt][0] *= c0; oacc[dt][1] *= c0;
            oacc[dt][2] *= c1; oacc[dt][3] *= c1;
        }
        __syncwarp();

        unsigned pa[2][4];
        #pragma unroll
        for (int s = 0; s < 2; s++) {
            pa[s][0] = smu[(wm + g    ) * 20 + s * 8 + t4    ];
            pa[s][1] = smu[(wm + g + 8) * 20 + s * 8 + t4    ];
            pa[s][2] = smu[(wm + g    ) * 20 + s * 8 + t4 + 4];
            pa[s][3] = smu[(wm + g + 8) * 20 + s * 8 + t4 + 4];
        }
        #pragma unroll
        for (int dt = 0; dt < 8; dt++) {
            unsigned vf[4];
            *(uint4*)&vf[0] = V4[lb + dt];
            mma_f16(oacc[dt], pa[0], vf[0], vf[1]);
            mma_f16(oacc[dt], pa[1], vf[2], vf[3]);
        }
    }

    float inv0 = 1.0f / l0;
    float inv1 = 1.0f / l1;
    int r0 = q0 + wm + g;
    int r1 = r0 + 8;
    #pragma unroll
    for (int dt = 0; dt < 8; dt++) {
        int d = dt * 8 + 2 * t4;
        float2 v0 = make_float2(oacc[dt][0] * inv0, oacc[dt][1] * inv0);
        float2 v1 = make_float2(oacc[dt][2] * inv1, oacc[dt][3] * inv1);
        *(float2*)&out[(b * SS + r0) * HIDN + h * HD + d] = v0;
        *(float2*)&out[(b * SS + r1) * HIDN + h * HD + d] = v1;
    }
}

// ---------------------------------------------------------------------------
extern "C" void kernel_launch(void* const* d_in, const int* in_sizes, int n_in,
                              void* d_out, int out_size) {
    const float* hs   = (const float*)d_in[0];
    const float* mask = (const float*)d_in[1];
    const float* Wq   = (const float*)d_in[2];
    const float* bq   = (const float*)d_in[3];
    const float* Wk   = (const float*)d_in[4];
    const float* bk   = (const float*)d_in[5];
    const float* Wv   = (const float*)d_in[6];
    const float* bv   = (const float*)d_in[7];
    float* out = (float*)d_out;

    static bool attr_set = false;
    if (!attr_set) {
        cudaFuncSetAttribute(qkv_gemm_fp16,
                             cudaFuncAttributeMaxDynamicSharedMemorySize,
                             QKV_SMEM_BYTES);
        cudaFuncSetAttribute(attn_fp16,
                             cudaFuncAttributeMaxDynamicSharedMemorySize,
                             ATTN_SMEM_BYTES);
        attr_set = true;
    }

    sincos_kernel<<<(SS * 32 + 255) / 256, 256>>>();
    round_xh<<<(BB * SS * HIDN / 8) / 256, 256>>>((const float4*)hs);
    wt_transpose_h<<<dim3(HIDN / 32, HIDN / 32, 3), 256>>>(Wq, Wk, Wv);
    qkv_gemm_fp16<<<dim3(30, 32), 256, QKV_SMEM_BYTES>>>(bq, bk, bv);
    rope_pack<<<dim3(SS / 32, BB * NH), 256>>>();
    attn_fp16<<<dim3(SS / 64, BB * NH), 128, ATTN_SMEM_BYTES>>>(mask, out);
}